// round 12
// baseline (speedup 1.0000x reference)
#include <cuda_runtime.h>
#include <cuda_fp16.h>
#include <math_constants.h>
#include <cstdint>

// Problem shape (fixed per reference setup_inputs)
#define B_  4
#define T_  4096
#define D_  1024
#define H_  64
#define BT_ (B_*T_)

// fp16 scratch — __device__ globals per alloc rules
__device__ __half g_qh[BT_*H_];   // holds q * (D^-0.5 * log2(e))  (prescaled!)
__device__ __half g_kh[BT_*H_];
__device__ __half g_vh[BT_*H_];
__device__ __half g_wh[3*D_*H_];  // pre-converted fp16 weights [w][k*64+n]

// ===========================================================================
// Baseline-PTX tensor helpers (sm_80+: ldmatrix + mma.sync + cp.async)
// ===========================================================================
__device__ __forceinline__ uint32_t smem_u32(const void* p) {
    uint32_t a;
    asm("{ .reg .u64 t; cvta.to.shared.u64 t, %1; cvt.u32.u64 %0, t; }"
        : "=r"(a) : "l"(p));
    return a;
}
__device__ __forceinline__ float ex2f(float x) {
    float y; asm("ex2.approx.ftz.f32 %0, %1;" : "=f"(y) : "f"(x)); return y;
}
__device__ __forceinline__ void ldsm4(uint32_t addr, uint32_t r[4]) {
    asm volatile("ldmatrix.sync.aligned.m8n8.x4.shared.b16 {%0,%1,%2,%3}, [%4];"
                 : "=r"(r[0]), "=r"(r[1]), "=r"(r[2]), "=r"(r[3]) : "r"(addr));
}
__device__ __forceinline__ void ldsm4t(uint32_t addr, uint32_t r[4]) {
    asm volatile("ldmatrix.sync.aligned.m8n8.x4.trans.shared.b16 {%0,%1,%2,%3}, [%4];"
                 : "=r"(r[0]), "=r"(r[1]), "=r"(r[2]), "=r"(r[3]) : "r"(addr));
}
__device__ __forceinline__ void mma16816(float c[4], const uint32_t a[4],
                                         uint32_t b0, uint32_t b1) {
    asm volatile("mma.sync.aligned.m16n8k16.row.col.f32.f16.f16.f32 "
                 "{%0,%1,%2,%3}, {%4,%5,%6,%7}, {%8,%9}, {%0,%1,%2,%3};"
                 : "+f"(c[0]), "+f"(c[1]), "+f"(c[2]), "+f"(c[3])
                 : "r"(a[0]), "r"(a[1]), "r"(a[2]), "r"(a[3]), "r"(b0), "r"(b1));
}
__device__ __forceinline__ uint32_t h2u(__half2 h) {
    return *reinterpret_cast<uint32_t*>(&h);
}
__device__ __forceinline__ void cp16(uint32_t dst, const void* src) {
    asm volatile("cp.async.cg.shared.global [%0], [%1], 16;" :: "r"(dst), "l"(src));
}
#define CP_COMMIT() asm volatile("cp.async.commit_group;" ::: "memory")
#define CP_WAIT(n)  asm volatile("cp.async.wait_group %0;" :: "n"(n) : "memory")
#define BAR_SYNC(id) asm volatile("bar.sync %0, 128;" :: "r"(id) : "memory")

// q prescale: D^-0.5 * log2(e)
#define QSCALE 0.045084220027780106f

// ===========================================================================
// Kernel 0: one-shot fp32 -> fp16 weight conversion
// ===========================================================================
__global__ __launch_bounds__(256) void convw_kernel(
    const float* __restrict__ Wq, const float* __restrict__ Wk,
    const float* __restrict__ Wv)
{
    int i = blockIdx.x * 256 + threadIdx.x;        // 49152 threads, 4 elems each
    int w = i >> 14;
    int r = (i & 16383) << 2;
    const float* W = (w == 0) ? Wq : (w == 1) ? Wk : Wv;
    float4 f = *(const float4*)&W[r];
    uint2 o;
    o.x = h2u(__floats2half2_rn(f.x, f.y));
    o.y = h2u(__floats2half2_rn(f.z, f.w));
    *(uint2*)&g_wh[w * (D_*H_) + r] = o;
}

// ===========================================================================
// Kernel 1: fused QKV projection, pipelined (proven R9, unchanged)
// ===========================================================================
#define PROJ_SMEM (18432 + 2*25600)   // 69632

__global__ __launch_bounds__(256, 1) void proj_kernel(const float* __restrict__ x)
{
    extern __shared__ char psm[];
    const int tid  = threadIdx.x;
    const int warp = tid >> 5, lane = tid & 31;
    const int la   = lane & 7;
    const int row0 = blockIdx.x * 128;
    const uint32_t smb = smem_u32(psm);

    float c[24][4];
    #pragma unroll
    for (int t = 0; t < 24; t++)
        #pragma unroll
        for (int j = 0; j < 4; j++) c[t][j] = 0.f;

    const uint32_t xaddr = smb + (warp * 16 + (lane & 8) + la) * 144 + (lane >> 4) * 16;
    const uint32_t wlo   = ((lane & 8) + la) * 400 + (lane >> 4) * 16;

    float4 xreg[8];
    #pragma unroll
    for (int t = 0; t < 8; t++) {
        int i = tid + t * 256, row = i >> 4, seg = i & 15;
        xreg[t] = *(const float4*)&x[(size_t)(row0 + row) * D_ + seg * 4];
    }
    #pragma unroll
    for (int t = 0; t < 6; t++) {
        int i = tid + t * 256;
        int w = i >> 9, rem = i & 511, k = rem >> 3, n16 = rem & 7;
        cp16(smb + 18432 + k * 400 + w * 128 + n16 * 16,
             g_wh + w * (D_*H_) + k * 64 + n16 * 8);
    }
    CP_COMMIT();

    for (int ci = 0; ci < 16; ci++) {
        CP_WAIT(0);
        #pragma unroll
        for (int t = 0; t < 8; t++) {
            int i = tid + t * 256, row = i >> 4, seg = i & 15;
            char* p = psm + row * 144 + seg * 8;
            *(__half2*)p       = __floats2half2_rn(xreg[t].x, xreg[t].y);
            *(__half2*)(p + 4) = __floats2half2_rn(xreg[t].z, xreg[t].w);
        }
        __syncthreads();

        if (ci < 15) {
            const int c0n = (ci + 1) * 64;
            #pragma unroll
            for (int t = 0; t < 8; t++) {
                int i = tid + t * 256, row = i >> 4, seg = i & 15;
                xreg[t] = *(const float4*)&x[(size_t)(row0 + row) * D_ + c0n + seg * 4];
            }
            #pragma unroll
            for (int t = 0; t < 6; t++) {
                int i = tid + t * 256;
                int w = i >> 9, rem = i & 511, k = rem >> 3, n16 = rem & 7;
                cp16(smb + 18432 + ((ci + 1) & 1) * 25600 + k * 400 + w * 128 + n16 * 16,
                     g_wh + w * (D_*H_) + (c0n + k) * 64 + n16 * 8);
            }
            CP_COMMIT();
        }

        const uint32_t waddr = smb + 18432 + (ci & 1) * 25600 + wlo;
        #pragma unroll
        for (int kk = 0; kk < 4; kk++) {
            uint32_t a[4];
            ldsm4(xaddr + kk * 32, a);
            #pragma unroll
            for (int np = 0; np < 12; np++) {
                uint32_t bm[4];
                ldsm4t(waddr + kk * 16 * 400 + np * 32, bm);
                mma16816(c[2 * np],     a, bm[0], bm[1]);
                mma16816(c[2 * np + 1], a, bm[2], bm[3]);
            }
        }
        __syncthreads();
    }

    // epilogue: q gets prescaled by QSCALE (folds softmax scale+log2e into MMA)
    #pragma unroll
    for (int nt = 0; nt < 8; nt++)
        #pragma unroll
        for (int j = 0; j < 4; j++) c[nt][j] *= QSCALE;

    const int rA = row0 + warp * 16 + (lane >> 2);
    #pragma unroll
    for (int nt = 0; nt < 24; nt++) {
        int w = nt >> 3;
        int col = (nt & 7) * 8 + (lane & 3) * 2;
        __half* gp = (w == 0) ? g_qh : (w == 1) ? g_kh : g_vh;
        *(__half2*)&gp[(size_t)rA * H_ + col]       = __floats2half2_rn(c[nt][0], c[nt][1]);
        *(__half2*)&gp[(size_t)(rA + 8) * H_ + col] = __floats2half2_rn(c[nt][2], c[nt][3]);
    }
}

// ===========================================================================
// Kernel 2: causal flash attention — 2 CTAs/SM occupancy version.
// One q-tile per CTA (grid 64 x B, big-qt-first). 256 thr = 2 key-split
// groups with independent 2-slot cp.async rings + named barriers.
// RACE FIX vs R11: trailing BAR_SYNC per iteration — with a 2-slot ring,
// iteration i+1's prefetch overwrites slot i&1, so all group warps must
// finish reading it first (3-slot rings were immune; 2-slot needs the bar).
// Inner loop processes the 64-key tile in two 32-key halves (low reg press).
// ===========================================================================
#define KVB 9216
#define G_RING (2*2*KVB)
#define SM_G0 9216
#define ATTN_SMEM_BYTES (SM_G0 + 2*G_RING)   // 82944

__global__ __launch_bounds__(256, 2) void attn_kernel(float* __restrict__ out)
{
    extern __shared__ __half dsm[];
    const int tid  = threadIdx.x;
    const int lane = tid & 31;
    const int la   = lane & 7;
    const int g    = tid >> 7;            // key-split group 0/1 (warps 0-3 / 4-7)
    const int wtid = tid & 127;
    const int wq   = (tid >> 5) & 3;      // 16-row sub-tile within group
    const int b    = blockIdx.y;
    const int qt   = 63 - (int)blockIdx.x;   // big workloads launch first
    const int q0   = qt * 64;

    const __half* qg = g_qh + (size_t)b * T_ * H_;
    const __half* kg = g_kh + (size_t)b * T_ * H_;
    const __half* vg = g_vh + (size_t)b * T_ * H_;

    const uint32_t smb   = smem_u32(dsm);
    const uint32_t qaddr = smb + (wq * 16 + (lane & 8) + la) * 144 + (lane >> 4) * 16;
    const uint32_t koff  = ((lane >> 4) * 8 + la) * 144 + ((lane >> 3) & 1) * 16;
    const uint32_t voff  = ((lane & 8) + la) * 144 + (lane >> 4) * 16;
    const uint32_t gring = smb + SM_G0 + g * G_RING;

    const int rloc = wq * 16 + (lane >> 2);
    // ones-column B-frag (B[k][n] = 1 iff n==0): lanes 0-3 hold (1.0,1.0)
    const uint32_t ones = ((lane >> 2) == 0) ? 0x3C003C00u : 0u;

    const int count = (qt >= g) ? ((qt - g) >> 1) + 1 : 0;

    // group prologue load: own tile kt=g into ring slot 0
    if (count > 0) {
        #pragma unroll
        for (int t = 0; t < 8; t++) {
            int i = wtid + t * 128;
            int kv = i >> 9, j = i & 511, row = j >> 3, seg = j & 7;
            const __half* src = (kv ? vg : kg) + (size_t)(g * 64 + row) * H_ + seg * 8;
            cp16(gring + kv * KVB + row * 144 + seg * 16, src);
        }
    }
    CP_COMMIT();

    // stage Q tile (whole CTA)
    #pragma unroll
    for (int t = 0; t < 2; t++) {
        int i = tid + t * 256, row = i >> 3, seg = i & 7;
        *(uint4*)((char*)dsm + row * 144 + seg * 16) =
            *(const uint4*)&qg[(size_t)(q0 + row) * H_ + seg * 8];
    }
    __syncthreads();

    uint32_t qa[4][4];
    #pragma unroll
    for (int kk = 0; kk < 4; kk++) ldsm4(qaddr + kk * 32, qa[kk]);

    float o[8][4], ol[4];
    #pragma unroll
    for (int t = 0; t < 8; t++)
        #pragma unroll
        for (int j = 0; j < 4; j++) o[t][j] = 0.f;
    #pragma unroll
    for (int j = 0; j < 4; j++) ol[j] = 0.f;

    for (int i = 0; i < count; i++) {
        const int kt = g + 2 * i;
        // prefetch own next tile into the other slot
        if (i + 1 < count) {
            const int ktn = kt + 2;
            const uint32_t nbase = gring + ((i + 1) & 1) * (2 * KVB);
            #pragma unroll
            for (int t = 0; t < 8; t++) {
                int ii = wtid + t * 128;
                int kv = ii >> 9, j = ii & 511, row = j >> 3, seg = j & 7;
                const __half* src = (kv ? vg : kg) + (size_t)(ktn * 64 + row) * H_ + seg * 8;
                cp16(nbase + kv * KVB + row * 144 + seg * 16, src);
            }
            CP_COMMIT();
            CP_WAIT(1);
        } else {
            CP_WAIT(0);
        }
        BAR_SYNC(g + 1);    // publish slot i&1 to the whole group

        const uint32_t kb = gring + (i & 1) * (2 * KVB);
        const uint32_t vb = kb + KVB;

        // process the 64-key tile in two 32-key halves (low register pressure)
        #pragma unroll
        for (int h = 0; h < 2; h++) {
            // ---- S_h = Q K_h^T (keys 32h..32h+31) ----
            float s[4][4];
            #pragma unroll
            for (int t = 0; t < 4; t++)
                #pragma unroll
                for (int j = 0; j < 4; j++) s[t][j] = 0.f;
            #pragma unroll
            for (int kk = 0; kk < 4; kk++) {
                #pragma unroll
                for (int np = 0; np < 2; np++) {
                    uint32_t km[4];
                    ldsm4(kb + koff + (2 * h + np) * 16 * 144 + kk * 32, km);
                    mma16816(s[2 * np],     qa[kk], km[0], km[1]);
                    mma16816(s[2 * np + 1], qa[kk], km[2], km[3]);
                }
            }

            // ---- causal mask (diagonal tile) ----
            if (kt == qt) {
                #pragma unroll
                for (int nt = 0; nt < 4; nt++) {
                    int key = 32 * h + nt * 8 + (lane & 3) * 2;
                    if (key     > rloc)     s[nt][0] = -CUDART_INF_F;
                    if (key + 1 > rloc)     s[nt][1] = -CUDART_INF_F;
                    if (key     > rloc + 8) s[nt][2] = -CUDART_INF_F;
                    if (key + 1 > rloc + 8) s[nt][3] = -CUDART_INF_F;
                }
            }

            // ---- softmax: p = 2^s (Q prescaled) ----
            uint32_t pa[2][4];
            #pragma unroll
            for (int nt = 0; nt < 4; nt++) {
                float p0 = ex2f(s[nt][0]);
                float p1 = ex2f(s[nt][1]);
                float p2 = ex2f(s[nt][2]);
                float p3 = ex2f(s[nt][3]);
                pa[nt >> 1][(nt & 1) * 2 + 0] = h2u(__floats2half2_rn(p0, p1));
                pa[nt >> 1][(nt & 1) * 2 + 1] = h2u(__floats2half2_rn(p2, p3));
            }

            // ---- O += P_h V_h ; l += P_h @ ones ----
            #pragma unroll
            for (int kc = 0; kc < 2; kc++) {
                #pragma unroll
                for (int hp = 0; hp < 4; hp++) {
                    uint32_t vm[4];
                    ldsm4t(vb + voff + (2 * h + kc) * 16 * 144 + hp * 32, vm);
                    mma16816(o[2 * hp],     pa[kc], vm[0], vm[1]);
                    mma16816(o[2 * hp + 1], pa[kc], vm[2], vm[3]);
                }
                mma16816(ol, pa[kc], ones, ones);
            }
        }

        BAR_SYNC(g + 1);    // all group warps done reading slot i&1
                            // (iteration i+1's prefetch overwrites it)
    }

    // l lives in quad-base lane, col 0: broadcast across the quad
    float l0 = __shfl_sync(0xffffffffu, ol[0], lane & ~3);
    float l1 = __shfl_sync(0xffffffffu, ol[2], lane & ~3);

    // ---- merge the two groups (merge area aliases g0 ring) ----
    float* mrgO = (float*)((char*)dsm + SM_G0);   // [64][68]
    float* mrgL = mrgO + 64 * 68;

    __syncthreads();   // both groups done computing; g0 ring free
    if (g == 1) {
        mrgL[rloc] = l0;  mrgL[rloc + 8] = l1;
        #pragma unroll
        for (int ht = 0; ht < 8; ht++) {
            int h = ht * 8 + (lane & 3) * 2;
            mrgO[rloc * 68 + h]           = o[ht][0];
            mrgO[rloc * 68 + h + 1]       = o[ht][1];
            mrgO[(rloc + 8) * 68 + h]     = o[ht][2];
            mrgO[(rloc + 8) * 68 + h + 1] = o[ht][3];
        }
    }
    __syncthreads();
    if (g == 0) {
        float inv0 = 1.0f / (l0 + mrgL[rloc]);
        float inv1 = 1.0f / (l1 + mrgL[rloc + 8]);
        const int rA = q0 + rloc;
        float* oA = out + ((size_t)b * T_ + rA) * H_;
        float* oB = oA + 8 * H_;
        #pragma unroll
        for (int ht = 0; ht < 8; ht++) {
            int h = ht * 8 + (lane & 3) * 2;
            float u0 = (o[ht][0] + mrgO[rloc * 68 + h])           * inv0;
            float u1 = (o[ht][1] + mrgO[rloc * 68 + h + 1])       * inv0;
            float u2 = (o[ht][2] + mrgO[(rloc + 8) * 68 + h])     * inv1;
            float u3 = (o[ht][3] + mrgO[(rloc + 8) * 68 + h + 1]) * inv1;
            *(float2*)&oA[h] = make_float2(u0, u1);
            *(float2*)&oB[h] = make_float2(u2, u3);
        }
    }
}

// ===========================================================================
extern "C" void kernel_launch(void* const* d_in, const int* in_sizes, int n_in,
                              void* d_out, int out_size)
{
    const float* x  = (const float*)d_in[0];
    const float* Wq = (const float*)d_in[1];
    const float* Wk = (const float*)d_in[2];
    const float* Wv = (const float*)d_in[3];
    float* out = (float*)d_out;
    (void)in_sizes; (void)n_in; (void)out_size;

    convw_kernel<<<192, 256>>>(Wq, Wk, Wv);

    cudaFuncSetAttribute(proj_kernel,
                         cudaFuncAttributeMaxDynamicSharedMemorySize, PROJ_SMEM);
    proj_kernel<<<BT_ / 128, 256, PROJ_SMEM>>>(x);

    cudaFuncSetAttribute(attn_kernel,
                         cudaFuncAttributeMaxDynamicSharedMemorySize,
                         ATTN_SMEM_BYTES);
    attn_kernel<<<dim3(64, B_), 256, ATTN_SMEM_BYTES>>>(out);
}

// round 13
// speedup vs baseline: 1.1342x; 1.1342x over previous
#include <cuda_runtime.h>
#include <cuda_fp16.h>
#include <math_constants.h>
#include <cstdint>

// Problem shape (fixed per reference setup_inputs)
#define B_  4
#define T_  4096
#define D_  1024
#define H_  64
#define BT_ (B_*T_)

// fp16 scratch — __device__ globals per alloc rules
__device__ __half g_qh[BT_*H_];   // holds q * (D^-0.5 * log2(e))  (prescaled!)
__device__ __half g_kh[BT_*H_];
__device__ __half g_vh[BT_*H_];
__device__ __half g_wh[3*D_*H_];  // pre-converted fp16 weights [w][k*64+n]

// ===========================================================================
// Baseline-PTX tensor helpers (sm_80+: ldmatrix + mma.sync + cp.async)
// ===========================================================================
__device__ __forceinline__ uint32_t smem_u32(const void* p) {
    uint32_t a;
    asm("{ .reg .u64 t; cvta.to.shared.u64 t, %1; cvt.u32.u64 %0, t; }"
        : "=r"(a) : "l"(p));
    return a;
}
__device__ __forceinline__ float ex2f(float x) {
    float y; asm("ex2.approx.ftz.f32 %0, %1;" : "=f"(y) : "f"(x)); return y;
}
__device__ __forceinline__ void ldsm4(uint32_t addr, uint32_t r[4]) {
    asm volatile("ldmatrix.sync.aligned.m8n8.x4.shared.b16 {%0,%1,%2,%3}, [%4];"
                 : "=r"(r[0]), "=r"(r[1]), "=r"(r[2]), "=r"(r[3]) : "r"(addr));
}
__device__ __forceinline__ void ldsm4t(uint32_t addr, uint32_t r[4]) {
    asm volatile("ldmatrix.sync.aligned.m8n8.x4.trans.shared.b16 {%0,%1,%2,%3}, [%4];"
                 : "=r"(r[0]), "=r"(r[1]), "=r"(r[2]), "=r"(r[3]) : "r"(addr));
}
__device__ __forceinline__ void mma16816(float c[4], const uint32_t a[4],
                                         uint32_t b0, uint32_t b1) {
    asm volatile("mma.sync.aligned.m16n8k16.row.col.f32.f16.f16.f32 "
                 "{%0,%1,%2,%3}, {%4,%5,%6,%7}, {%8,%9}, {%0,%1,%2,%3};"
                 : "+f"(c[0]), "+f"(c[1]), "+f"(c[2]), "+f"(c[3])
                 : "r"(a[0]), "r"(a[1]), "r"(a[2]), "r"(a[3]), "r"(b0), "r"(b1));
}
__device__ __forceinline__ uint32_t h2u(__half2 h) {
    return *reinterpret_cast<uint32_t*>(&h);
}
__device__ __forceinline__ void cp16(uint32_t dst, const void* src) {
    asm volatile("cp.async.cg.shared.global [%0], [%1], 16;" :: "r"(dst), "l"(src));
}
#define CP_COMMIT() asm volatile("cp.async.commit_group;" ::: "memory")
#define CP_WAIT(n)  asm volatile("cp.async.wait_group %0;" :: "n"(n) : "memory")
#define BAR_SYNC(id) asm volatile("bar.sync %0, 128;" :: "r"(id) : "memory")

// q prescale: D^-0.5 * log2(e)
#define QSCALE 0.045084220027780106f

// ===========================================================================
// Kernel 0: one-shot fp32 -> fp16 weight conversion
// ===========================================================================
__global__ __launch_bounds__(256) void convw_kernel(
    const float* __restrict__ Wq, const float* __restrict__ Wk,
    const float* __restrict__ Wv)
{
    int i = blockIdx.x * 256 + threadIdx.x;        // 49152 threads, 4 elems each
    int w = i >> 14;
    int r = (i & 16383) << 2;
    const float* W = (w == 0) ? Wq : (w == 1) ? Wk : Wv;
    float4 f = *(const float4*)&W[r];
    uint2 o;
    o.x = h2u(__floats2half2_rn(f.x, f.y));
    o.y = h2u(__floats2half2_rn(f.z, f.w));
    *(uint2*)&g_wh[w * (D_*H_) + r] = o;
}

// ===========================================================================
// Kernel 1: fused QKV projection — 128 thr / 64 rows per CTA, grid 256.
// Same per-warp structure as the proven R9 proj (4 warps x 16 rows, N=192),
// but half-size CTAs: 2 CTAs/SM (regs ~170 x 256 thr, smem 60416 x 2 fits),
// all 148 SMs covered in one wave, CTA-level memory/compute overlap.
// Dyn smem: Xs [0,9216) stride 144 | Wb0 [9216,+25600) | Wb1 (+25600).
// ===========================================================================
#define PROJ_SMEM (9216 + 2*25600)   // 60416

__global__ __launch_bounds__(128, 2) void proj_kernel(const float* __restrict__ x)
{
    extern __shared__ char psm[];
    const int tid  = threadIdx.x;
    const int warp = tid >> 5, lane = tid & 31;
    const int la   = lane & 7;
    const int row0 = blockIdx.x * 64;
    const uint32_t smb = smem_u32(psm);

    float c[24][4];
    #pragma unroll
    for (int t = 0; t < 24; t++)
        #pragma unroll
        for (int j = 0; j < 4; j++) c[t][j] = 0.f;

    const uint32_t xaddr = smb + (warp * 16 + (lane & 8) + la) * 144 + (lane >> 4) * 16;
    const uint32_t wlo   = ((lane & 8) + la) * 400 + (lane >> 4) * 16;

    // prologue: LDG X chunk 0 -> regs; cp.async W chunk 0 -> Wb0
    float4 xreg[8];
    #pragma unroll
    for (int t = 0; t < 8; t++) {
        int i = tid + t * 128, row = i >> 4, seg = i & 15;
        xreg[t] = *(const float4*)&x[(size_t)(row0 + row) * D_ + seg * 4];
    }
    #pragma unroll
    for (int t = 0; t < 12; t++) {
        int i = tid + t * 128;
        int w = i >> 9, rem = i & 511, k = rem >> 3, n16 = rem & 7;
        cp16(smb + 9216 + k * 400 + w * 128 + n16 * 16,
             g_wh + w * (D_*H_) + k * 64 + n16 * 8);
    }
    CP_COMMIT();

    for (int ci = 0; ci < 16; ci++) {
        CP_WAIT(0);
        // STS X chunk ci (fp32 regs -> fp16 smem)
        #pragma unroll
        for (int t = 0; t < 8; t++) {
            int i = tid + t * 128, row = i >> 4, seg = i & 15;
            char* p = psm + row * 144 + seg * 8;
            *(__half2*)p       = __floats2half2_rn(xreg[t].x, xreg[t].y);
            *(__half2*)(p + 4) = __floats2half2_rn(xreg[t].z, xreg[t].w);
        }
        __syncthreads();

        // prefetch chunk ci+1 (X -> regs, W -> other buffer)
        if (ci < 15) {
            const int c0n = (ci + 1) * 64;
            #pragma unroll
            for (int t = 0; t < 8; t++) {
                int i = tid + t * 128, row = i >> 4, seg = i & 15;
                xreg[t] = *(const float4*)&x[(size_t)(row0 + row) * D_ + c0n + seg * 4];
            }
            #pragma unroll
            for (int t = 0; t < 12; t++) {
                int i = tid + t * 128;
                int w = i >> 9, rem = i & 511, k = rem >> 3, n16 = rem & 7;
                cp16(smb + 9216 + ((ci + 1) & 1) * 25600 + k * 400 + w * 128 + n16 * 16,
                     g_wh + w * (D_*H_) + (c0n + k) * 64 + n16 * 8);
            }
            CP_COMMIT();
        }

        // compute on chunk ci
        const uint32_t waddr = smb + 9216 + (ci & 1) * 25600 + wlo;
        #pragma unroll
        for (int kk = 0; kk < 4; kk++) {
            uint32_t a[4];
            ldsm4(xaddr + kk * 32, a);
            #pragma unroll
            for (int np = 0; np < 12; np++) {
                uint32_t bm[4];
                ldsm4t(waddr + kk * 16 * 400 + np * 32, bm);
                mma16816(c[2 * np],     a, bm[0], bm[1]);
                mma16816(c[2 * np + 1], a, bm[2], bm[3]);
            }
        }
        __syncthreads();
    }

    // epilogue: q gets prescaled by QSCALE (folds softmax scale+log2e into MMA)
    #pragma unroll
    for (int nt = 0; nt < 8; nt++)
        #pragma unroll
        for (int j = 0; j < 4; j++) c[nt][j] *= QSCALE;

    const int rA = row0 + warp * 16 + (lane >> 2);
    #pragma unroll
    for (int nt = 0; nt < 24; nt++) {
        int w = nt >> 3;
        int col = (nt & 7) * 8 + (lane & 3) * 2;
        __half* gp = (w == 0) ? g_qh : (w == 1) ? g_kh : g_vh;
        *(__half2*)&gp[(size_t)rA * H_ + col]       = __floats2half2_rn(c[nt][0], c[nt][1]);
        *(__half2*)&gp[(size_t)(rA + 8) * H_ + col] = __floats2half2_rn(c[nt][2], c[nt][3]);
    }
}

// ===========================================================================
// Kernel 2: causal flash attention — EXACT R9 (proven 68.3us config).
// Key-split groups, independent per-group 3-slot cp.async rings + named
// barriers, balanced (qt, 63-qt) pairing, p = 2^s softmax (Q prescaled),
// l via ones-column MMA on the tensor pipe.
// ===========================================================================
#define KVB 9216
#define G_RING (3*2*KVB)
#define SM_G0 9216
#define ATTN_SMEM_BYTES (SM_G0 + 2*G_RING)   // 119808

__global__ __launch_bounds__(256, 1) void attn_kernel(float* __restrict__ out)
{
    extern __shared__ __half dsm[];
    const int tid  = threadIdx.x;
    const int lane = tid & 31;
    const int la   = lane & 7;
    const int g    = tid >> 7;            // key-split group 0/1 (warps 0-3 / 4-7)
    const int wtid = tid & 127;
    const int wq   = (tid >> 5) & 3;      // 16-row sub-tile within group
    const int b    = blockIdx.y;

    const __half* qg = g_qh + (size_t)b * T_ * H_;
    const __half* kg = g_kh + (size_t)b * T_ * H_;
    const __half* vg = g_vh + (size_t)b * T_ * H_;

    const uint32_t smb   = smem_u32(dsm);
    const uint32_t qaddr = smb + (wq * 16 + (lane & 8) + la) * 144 + (lane >> 4) * 16;
    const uint32_t koff  = ((lane >> 4) * 8 + la) * 144 + ((lane >> 3) & 1) * 16;
    const uint32_t voff  = ((lane & 8) + la) * 144 + (lane >> 4) * 16;
    const uint32_t gring = smb + SM_G0 + g * G_RING;

    const int rloc = wq * 16 + (lane >> 2);
    // ones-column B-frag (B[k][n] = 1 iff n==0): lanes 0-3 hold (1.0,1.0)
    const uint32_t ones = ((lane >> 2) == 0) ? 0x3C003C00u : 0u;

    #pragma unroll 1
    for (int hf = 0; hf < 2; hf++) {
        const int qt = hf ? (63 - (int)blockIdx.x) : (int)blockIdx.x;
        const int q0 = qt * 64;
        const int count = (qt >= g) ? ((qt - g) >> 1) + 1 : 0;

        // group prologue load: own tile kt=g into ring slot 0
        if (count > 0) {
            #pragma unroll
            for (int t = 0; t < 8; t++) {
                int i = wtid + t * 128;
                int kv = i >> 9, j = i & 511, row = j >> 3, seg = j & 7;
                const __half* src = (kv ? vg : kg) + (size_t)(g * 64 + row) * H_ + seg * 8;
                cp16(gring + kv * KVB + row * 144 + seg * 16, src);
            }
        }
        CP_COMMIT();

        // stage Q tile (whole CTA)
        #pragma unroll
        for (int t = 0; t < 2; t++) {
            int i = tid + t * 256, row = i >> 3, seg = i & 7;
            *(uint4*)((char*)dsm + row * 144 + seg * 16) =
                *(const uint4*)&qg[(size_t)(q0 + row) * H_ + seg * 8];
        }
        __syncthreads();

        uint32_t qa[4][4];
        #pragma unroll
        for (int kk = 0; kk < 4; kk++) ldsm4(qaddr + kk * 32, qa[kk]);

        float o[8][4], ol[4];
        #pragma unroll
        for (int t = 0; t < 8; t++)
            #pragma unroll
            for (int j = 0; j < 4; j++) o[t][j] = 0.f;
        #pragma unroll
        for (int j = 0; j < 4; j++) ol[j] = 0.f;

        for (int i = 0; i < count; i++) {
            const int kt = g + 2 * i;
            // prefetch own next tile into slot (i+1)%3
            if (i + 1 < count) {
                const int ktn = kt + 2;
                const uint32_t nbase = gring + ((i + 1) % 3) * (2 * KVB);
                #pragma unroll
                for (int t = 0; t < 8; t++) {
                    int ii = wtid + t * 128;
                    int kv = ii >> 9, j = ii & 511, row = j >> 3, seg = j & 7;
                    const __half* src = (kv ? vg : kg) + (size_t)(ktn * 64 + row) * H_ + seg * 8;
                    cp16(nbase + kv * KVB + row * 144 + seg * 16, src);
                }
                CP_COMMIT();
                CP_WAIT(1);
            } else {
                CP_WAIT(0);
            }
            BAR_SYNC(g + 1);    // group-local: publish this group's tile

            const uint32_t kb = gring + (i % 3) * (2 * KVB);
            const uint32_t vb = kb + KVB;

            // ---- S = Q K^T (s already in log2 space via Q prescale) ----
            float s[8][4];
            #pragma unroll
            for (int t = 0; t < 8; t++)
                #pragma unroll
                for (int j = 0; j < 4; j++) s[t][j] = 0.f;
            #pragma unroll
            for (int kk = 0; kk < 4; kk++) {
                #pragma unroll
                for (int np = 0; np < 4; np++) {
                    uint32_t km[4];
                    ldsm4(kb + koff + np * 16 * 144 + kk * 32, km);
                    mma16816(s[2 * np],     qa[kk], km[0], km[1]);
                    mma16816(s[2 * np + 1], qa[kk], km[2], km[3]);
                }
            }

            // ---- causal mask (diagonal tile) ----
            if (kt == qt) {
                #pragma unroll
                for (int nt = 0; nt < 8; nt++) {
                    int key = nt * 8 + (lane & 3) * 2;
                    if (key     > rloc)     s[nt][0] = -CUDART_INF_F;
                    if (key + 1 > rloc)     s[nt][1] = -CUDART_INF_F;
                    if (key     > rloc + 8) s[nt][2] = -CUDART_INF_F;
                    if (key + 1 > rloc + 8) s[nt][3] = -CUDART_INF_F;
                }
            }

            // ---- softmax: p = 2^s, pack to half2 a-frags ----
            uint32_t pa[4][4];
            #pragma unroll
            for (int nt = 0; nt < 8; nt++) {
                float p0 = ex2f(s[nt][0]);
                float p1 = ex2f(s[nt][1]);
                float p2 = ex2f(s[nt][2]);
                float p3 = ex2f(s[nt][3]);
                pa[nt >> 1][(nt & 1) * 2 + 0] = h2u(__floats2half2_rn(p0, p1));
                pa[nt >> 1][(nt & 1) * 2 + 1] = h2u(__floats2half2_rn(p2, p3));
            }

            // ---- O += P V ; l += P @ ones (tensor pipe) ----
            #pragma unroll
            for (int kk = 0; kk < 4; kk++) {
                #pragma unroll
                for (int hp = 0; hp < 4; hp++) {
                    uint32_t vm[4];
                    ldsm4t(vb + voff + kk * 16 * 144 + hp * 32, vm);
                    mma16816(o[2 * hp],     pa[kk], vm[0], vm[1]);
                    mma16816(o[2 * hp + 1], pa[kk], vm[2], vm[3]);
                }
                mma16816(ol, pa[kk], ones, ones);
            }
        }

        // l lives in quad-base lane, col 0: broadcast across the quad
        float l0 = __shfl_sync(0xffffffffu, ol[0], lane & ~3);
        float l1 = __shfl_sync(0xffffffffu, ol[2], lane & ~3);

        // ---- merge the two groups (merge area aliases g0 ring) ----
        float* mrgO = (float*)((char*)dsm + SM_G0);   // [64][68]
        float* mrgL = mrgO + 64 * 68;

        __syncthreads();   // both groups done computing; g0 ring free
        if (g == 1) {
            mrgL[rloc] = l0;  mrgL[rloc + 8] = l1;
            #pragma unroll
            for (int ht = 0; ht < 8; ht++) {
                int h = ht * 8 + (lane & 3) * 2;
                mrgO[rloc * 68 + h]           = o[ht][0];
                mrgO[rloc * 68 + h + 1]       = o[ht][1];
                mrgO[(rloc + 8) * 68 + h]     = o[ht][2];
                mrgO[(rloc + 8) * 68 + h + 1] = o[ht][3];
            }
        }
        __syncthreads();
        if (g == 0) {
            float inv0 = 1.0f / (l0 + mrgL[rloc]);
            float inv1 = 1.0f / (l1 + mrgL[rloc + 8]);
            const int rA = q0 + rloc;
            float* oA = out + ((size_t)b * T_ + rA) * H_;
            float* oB = oA + 8 * H_;
            #pragma unroll
            for (int ht = 0; ht < 8; ht++) {
                int h = ht * 8 + (lane & 3) * 2;
                float u0 = (o[ht][0] + mrgO[rloc * 68 + h])           * inv0;
                float u1 = (o[ht][1] + mrgO[rloc * 68 + h + 1])       * inv0;
                float u2 = (o[ht][2] + mrgO[(rloc + 8) * 68 + h])     * inv1;
                float u3 = (o[ht][3] + mrgO[(rloc + 8) * 68 + h + 1]) * inv1;
                *(float2*)&oA[h] = make_float2(u0, u1);
                *(float2*)&oB[h] = make_float2(u2, u3);
            }
        }
        __syncthreads();   // merge reads done before next hf overwrites rings/Q
    }
}

// ===========================================================================
extern "C" void kernel_launch(void* const* d_in, const int* in_sizes, int n_in,
                              void* d_out, int out_size)
{
    const float* x  = (const float*)d_in[0];
    const float* Wq = (const float*)d_in[1];
    const float* Wk = (const float*)d_in[2];
    const float* Wv = (const float*)d_in[3];
    float* out = (float*)d_out;
    (void)in_sizes; (void)n_in; (void)out_size;

    convw_kernel<<<192, 256>>>(Wq, Wk, Wv);

    cudaFuncSetAttribute(proj_kernel,
                         cudaFuncAttributeMaxDynamicSharedMemorySize, PROJ_SMEM);
    proj_kernel<<<BT_ / 64, 128, PROJ_SMEM>>>(x);

    cudaFuncSetAttribute(attn_kernel,
                         cudaFuncAttributeMaxDynamicSharedMemorySize,
                         ATTN_SMEM_BYTES);
    attn_kernel<<<dim3(32, B_), 256, ATTN_SMEM_BYTES>>>(out);
}